// round 1
// baseline (speedup 1.0000x reference)
#include <cuda_runtime.h>
#include <math.h>
#include <stdint.h>

// Problem constants
#define BB   2
#define LL   2048
#define HH   16
#define DD   64
#define HIDN 1024
#define NBR  4
#define NROWS (BB*LL*HH)     // 65536 gate rows
#define NBL   (BB*LL)        // 4096 (b,l) positions
#define NOUT  128            // 2*D hidden layer width

// Scratch (static device globals — no allocation)
__device__ float g_wsum[12 * 128];          // column sums of W1 stat blocks
__device__ float g_hidpart[NBL * NOUT];     // hidden @ W1[0:1024] + b1

// ---- packed fp32x2 helpers (FFMA2: 2x fp32 throughput vs 3-reg FFMA) ----
__device__ __forceinline__ void ffma2(unsigned long long& d,
                                      unsigned long long a,
                                      unsigned long long b) {
    asm("fma.rn.f32x2 %0, %1, %2, %0;" : "+l"(d) : "l"(a), "l"(b));
}
__device__ __forceinline__ unsigned long long pack2(float x, float y) {
    unsigned long long r;
    asm("mov.b64 %0, {%1, %2};" : "=l"(r) : "f"(x), "f"(y));
    return r;
}
__device__ __forceinline__ float2 unpack2(unsigned long long v) {
    float2 f;
    asm("mov.b64 {%0, %1}, %2;" : "=f"(f.x), "=f"(f.y) : "l"(v));
    return f;
}

// ============================================================================
// Kernel 1: column sums of the 12 stat blocks of W1 (rows 1024..1791)
// stat block ps = p*3+s occupies rows 1024 + ps*64 .. +63  (p*192+s*64 == ps*64)
// ============================================================================
__global__ void wsum_kernel(const float* __restrict__ W1) {
    int ps = blockIdx.x;          // 0..11
    int j  = threadIdx.x;         // 0..127
    int base = 1024 + ps * 64;
    float s = 0.f;
#pragma unroll 8
    for (int d = 0; d < 64; d++) s += W1[(base + d) * 128 + j];
    g_wsum[ps * 128 + j] = s;
}

// ============================================================================
// Kernel 2: g_hidpart[m][j] = sum_k hidden[m][k] * W1[k][j] + b1[j]
//           M=4096, K=1024, N=128. 128 blocks x 256 thr, Mtile=32, Ktile=32.
// ============================================================================
__global__ __launch_bounds__(256) void hid_gemm_kernel(
    const float* __restrict__ hidden,
    const float* __restrict__ W1,
    const float* __restrict__ b1)
{
    __shared__ float A_s[32][33];    // [row][k], padded
    __shared__ float B_s[32][128];   // [k][col]
    int tid = threadIdx.x;
    int tc = tid & 31;               // col group: cols 4*tc..4*tc+3
    int tr = tid >> 5;               // row group: rows tr*4..tr*4+3
    int m0 = blockIdx.x * 32;

    unsigned long long acc[4][2];
#pragma unroll
    for (int j = 0; j < 4; j++) { acc[j][0] = 0ull; acc[j][1] = 0ull; }

    for (int k0 = 0; k0 < HIDN; k0 += 32) {
        for (int i = tid; i < 32 * 32; i += 256) {
            int r = i >> 5, kk = i & 31;
            A_s[r][kk] = hidden[(m0 + r) * HIDN + k0 + kk];
        }
        for (int i = tid; i < 32 * 128; i += 256) {
            int kk = i >> 7, c = i & 127;
            B_s[kk][c] = W1[(k0 + kk) * 128 + c];
        }
        __syncthreads();
#pragma unroll 8
        for (int kk = 0; kk < 32; kk++) {
            ulonglong2 wv = *(const ulonglong2*)&B_s[kk][tc * 4];
#pragma unroll
            for (int j = 0; j < 4; j++) {
                float xv = A_s[tr * 4 + j][kk];
                unsigned long long xx = pack2(xv, xv);
                ffma2(acc[j][0], wv.x, xx);
                ffma2(acc[j][1], wv.y, xx);
            }
        }
        __syncthreads();
    }
    float bv0 = b1[tc * 4 + 0], bv1 = b1[tc * 4 + 1];
    float bv2 = b1[tc * 4 + 2], bv3 = b1[tc * 4 + 3];
#pragma unroll
    for (int j = 0; j < 4; j++) {
        float2 a0 = unpack2(acc[j][0]), a1 = unpack2(acc[j][1]);
        float4 v = make_float4(a0.x + bv0, a0.y + bv1, a1.x + bv2, a1.y + bv3);
        *(float4*)&g_hidpart[(m0 + tr * 4 + j) * 128 + tc * 4] = v;
    }
}

// ============================================================================
// Kernel 3: main per-head kernel. Persistent CTAs; full branch weight block
// (256x128 = 128KB) resident in SMEM. Tile of TM=64 rows per iteration.
// ============================================================================
#define TM 64
#define XPITCH 257   // pad row to 257 floats -> conflict-free stats phase

struct SmemMain {
    float W[256 * 128];        // 131072 B branch weight block (rows 1792..2047 of W1)
    float x[TM * XPITCH];      // 65792 B  per-row branch concat [64][256] padded
    float wsum[12 * 128];      //  6144 B
    float stat[TM * 12];       //  3072 B  [row][p*3+s]
    float w2[128 * 4];         //  2048 B
};                              // = 208128 B total

__global__ __launch_bounds__(256, 1) void main_kernel(
    const float* __restrict__ br0, const float* __restrict__ br1,
    const float* __restrict__ br2, const float* __restrict__ br3,
    const float* __restrict__ W1, const float* __restrict__ W2,
    const float* __restrict__ b2, const float* __restrict__ eps_floor,
    const float* __restrict__ temp, float* __restrict__ out)
{
    extern __shared__ float smem_raw[];
    SmemMain* S = (SmemMain*)smem_raw;
    int tid = threadIdx.x;
    int tc = tid & 31;     // col group: cols 4*tc..4*tc+3
    int tr = tid >> 5;     // row group: rows tr*8..tr*8+7

    // One-time loads: W branch block, wsum, W2
    {
        const float4* Wb = (const float4*)(W1 + 1792 * 128);
        for (int i = tid; i < 256 * 128 / 4; i += 256) ((float4*)S->W)[i] = Wb[i];
        for (int i = tid; i < 12 * 128; i += 256) S->wsum[i] = g_wsum[i];
        for (int i = tid; i < 512; i += 256) S->w2[i] = W2[i];
    }

    const float* brs0 = br0; const float* brs1 = br1;
    const float* brs2 = br2; const float* brs3 = br3;

    const int ntiles = NROWS / TM;   // 1024
    for (int tile = blockIdx.x; tile < ntiles; tile += gridDim.x) {
        int rg0 = tile * TM;
        __syncthreads();   // also covers the one-time loads on first iteration

        // ---- load x tile: x[r][p*64+d] = branch_p[rg0+r][d] ----
        {
            const float* bp;
#pragma unroll
            for (int p = 0; p < 4; p++) {
                bp = (p == 0) ? brs0 : (p == 1) ? brs1 : (p == 2) ? brs2 : brs3;
                bp += (size_t)rg0 * 64;
                for (int i = tid; i < TM * 64; i += 256) {
                    int r = i >> 6, d = i & 63;
                    S->x[r * XPITCH + p * 64 + d] = bp[i];
                }
            }
        }
        __syncthreads();

        // ---- stats: one thread per (row, branch) ----
        {
            int r = tid & 63, p = tid >> 6;
            const float* xr = &S->x[r * XPITCH + p * 64];
            float sum = 0.f, sq = 0.f, mx = -INFINITY;
#pragma unroll 8
            for (int d = 0; d < 64; d++) {
                float v = xr[d];
                sum += v; sq += v * v; mx = fmaxf(mx, v);
            }
            float mean = sum * (1.0f / 64.0f);
            float rms = sqrtf(fmaxf(sq * (1.0f / 64.0f), 1e-8f));
            S->stat[r * 12 + p * 3 + 0] = mean;
            S->stat[r * 12 + p * 3 + 1] = rms;
            S->stat[r * 12 + p * 3 + 2] = mx;
        }
        __syncthreads();

        // ---- branch GEMM: 8 rows x 4 cols per thread, f32x2 FMAs ----
        unsigned long long acc[8][2];
#pragma unroll
        for (int j = 0; j < 8; j++) { acc[j][0] = 0ull; acc[j][1] = 0ull; }
        const float* xb = &S->x[tr * 8 * XPITCH];
#pragma unroll 2
        for (int k = 0; k < 256; k++) {
            ulonglong2 wv = *(const ulonglong2*)&S->W[k * 128 + tc * 4];
#pragma unroll
            for (int j = 0; j < 8; j++) {
                float xv = xb[j * XPITCH + k];          // warp-broadcast LDS
                unsigned long long xx = pack2(xv, xv);
                ffma2(acc[j][0], wv.x, xx);
                ffma2(acc[j][1], wv.y, xx);
            }
        }

        // ---- epilogue ----
        float4 w2c[4];
#pragma unroll
        for (int c = 0; c < 4; c++) w2c[c] = *(const float4*)&S->w2[(tc * 4 + c) * 4];

#pragma unroll
        for (int j = 0; j < 8; j++) {
            int r = tr * 8 + j;
            int rg = rg0 + r;                 // global gate row
            float2 a0 = unpack2(acc[j][0]), a1 = unpack2(acc[j][1]);
            float h0 = a0.x, h1 = a0.y, h2 = a1.x, h3 = a1.y;

            // shared hidden contribution (already has b1)
            float4 hid = *(const float4*)&g_hidpart[(rg >> 4) * 128 + tc * 4];
            h0 += hid.x; h1 += hid.y; h2 += hid.z; h3 += hid.w;

            // stats contribution: 12 scalars x column-sum vectors
            const float* st = &S->stat[r * 12];
#pragma unroll
            for (int ps = 0; ps < 12; ps++) {
                float sv = st[ps];
                float4 wv = *(const float4*)&S->wsum[ps * 128 + tc * 4];
                h0 += sv * wv.x; h1 += sv * wv.y; h2 += sv * wv.z; h3 += sv * wv.w;
            }

            // exact GELU then second layer partials (this lane's 4 cols)
            float lp0 = 0.f, lp1 = 0.f, lp2 = 0.f, lp3 = 0.f;
            float hv[4] = {h0, h1, h2, h3};
#pragma unroll
            for (int c = 0; c < 4; c++) {
                float g = 0.5f * hv[c] * (1.0f + erff(hv[c] * 0.7071067811865476f));
                lp0 += g * w2c[c].x; lp1 += g * w2c[c].y;
                lp2 += g * w2c[c].z; lp3 += g * w2c[c].w;
            }
            // warp reduction over the 32 col-groups (128 cols)
#pragma unroll
            for (int off = 16; off > 0; off >>= 1) {
                lp0 += __shfl_xor_sync(0xffffffffu, lp0, off);
                lp1 += __shfl_xor_sync(0xffffffffu, lp1, off);
                lp2 += __shfl_xor_sync(0xffffffffu, lp2, off);
                lp3 += __shfl_xor_sync(0xffffffffu, lp3, off);
            }
            if (tc == 0) {
                int hh = rg & (HH - 1);
                float t = fminf(fmaxf(temp[hh], 0.2f), 10.0f);
                float invt = 1.0f / t;
                float q0 = (lp0 + b2[0]) * invt;
                float q1 = (lp1 + b2[1]) * invt;
                float q2 = (lp2 + b2[2]) * invt;
                float q3 = (lp3 + b2[3]) * invt;
                float m = fmaxf(fmaxf(q0, q1), fmaxf(q2, q3));
                float e0 = expf(q0 - m), e1 = expf(q1 - m);
                float e2 = expf(q2 - m), e3 = expf(q3 - m);
                float inv = 1.0f / (e0 + e1 + e2 + e3);
                float w0 = e0 * inv, w1 = e1 * inv, w2v = e2 * inv, w3 = e3 * inv;
                const float* ef = eps_floor + hh * 4;
                w0 = fmaxf(w0, fminf(fmaxf(ef[0], 1e-7f), 0.1f));
                w1 = fmaxf(w1, fminf(fmaxf(ef[1], 1e-7f), 0.1f));
                w2v = fmaxf(w2v, fminf(fmaxf(ef[2], 1e-7f), 0.1f));
                w3 = fmaxf(w3, fminf(fmaxf(ef[3], 1e-7f), 0.1f));
                float inv2 = 1.0f / (w0 + w1 + w2v + w3);
                float4 o = make_float4(w0 * inv2, w1 * inv2, w2v * inv2, w3 * inv2);
                *(float4*)&out[(size_t)rg * 4] = o;
            }
        }
    }
}

// ============================================================================
// Launch
// ============================================================================
extern "C" void kernel_launch(void* const* d_in, const int* in_sizes, int n_in,
                              void* d_out, int out_size)
{
    const float* hidden = (const float*)d_in[0];
    const float* br0    = (const float*)d_in[1];
    const float* br1    = (const float*)d_in[2];
    const float* br2    = (const float*)d_in[3];
    const float* br3    = (const float*)d_in[4];
    const float* W1     = (const float*)d_in[5];
    const float* b1     = (const float*)d_in[6];
    const float* W2     = (const float*)d_in[7];
    const float* b2     = (const float*)d_in[8];
    const float* eps    = (const float*)d_in[9];
    const float* temp   = (const float*)d_in[10];
    float* out = (float*)d_out;

    cudaFuncSetAttribute(main_kernel, cudaFuncAttributeMaxDynamicSharedMemorySize,
                         (int)sizeof(SmemMain));

    wsum_kernel<<<12, 128>>>(W1);
    hid_gemm_kernel<<<NBL / 32, 256>>>(hidden, W1, b1);
    main_kernel<<<152, 256, sizeof(SmemMain)>>>(br0, br1, br2, br3, W1, W2,
                                                b2, eps, temp, out);
}